// round 7
// baseline (speedup 1.0000x reference)
#include <cuda_runtime.h>

#define NN 50000
#define EE 800000
#define HH 4

// ---------------- scratch (static __device__, no allocations) ----------------
__device__ __align__(16) float g_xl[NN * 256];      // xl1 [N,256] then xl2 [N,128]
__device__ __align__(16) float g_out1[NN * 64];     // layer-1 output [N,64]
__device__ __align__(16) float g_P[NN * 128];       // node projections for edge MLP
__device__ __align__(16) float g_alpha[EE * 4];     // exp(logit), edge order (layer 2 only)
__device__ __align__(16) float g_alpha_s[EE * 4];   // exp(logit), dst-sorted order
__device__ __align__(16) float g_asrc[NN * 4];
__device__ __align__(16) float g_adst[NN * 4];
__device__ __align__(16) float g_nodeR[NN * 4];     // per-node 1/(sum+eps) (layer 2)
__device__ int g_deg[NN];
__device__ int g_cursor[NN];
__device__ int g_rowptr[NN + 1];
__device__ int g_pos[EE];             // edge id -> sorted position
__device__ int g_srcs[EE];            // src node per sorted edge

// ---------------- CSR build ----------------
__global__ void zero_counts_kernel() {
    int i = blockIdx.x * blockDim.x + threadIdx.x;
    if (i < NN) { g_deg[i] = 0; g_cursor[i] = 0; }
}

__global__ void hist_kernel(const int* __restrict__ ei) {
    int e = blockIdx.x * blockDim.x + threadIdx.x;
    if (e >= EE) return;
    atomicAdd(&g_deg[ei[EE + e]], 1);
}

__global__ void scan_kernel() {
    __shared__ int sh[1024];
    int t = threadIdx.x;
    const int chunk = (NN + 1023) / 1024;
    int beg = t * chunk;
    int end = beg + chunk; if (end > NN) end = NN; if (beg > NN) beg = NN;
    int s = 0;
    for (int i = beg; i < end; i++) s += g_deg[i];
    sh[t] = s;
    __syncthreads();
    for (int off = 1; off < 1024; off <<= 1) {
        int v = (t >= off) ? sh[t - off] : 0;
        __syncthreads();
        sh[t] += v;
        __syncthreads();
    }
    int run = (t > 0) ? sh[t - 1] : 0;
    for (int i = beg; i < end; i++) { g_rowptr[i] = run; run += g_deg[i]; }
    if (t == 0) g_rowptr[NN] = sh[1023];
}

__global__ void scatter_kernel(const int* __restrict__ ei) {
    int e = blockIdx.x * blockDim.x + threadIdx.x;
    if (e >= EE) return;
    int d = ei[EE + e];
    int pos = g_rowptr[d] + atomicAdd(&g_cursor[d], 1);
    g_pos[e] = pos;
    g_srcs[pos] = ei[e];
}

// ---------------- SGEMM + fused attention dots ----------------
// C[MxNd] = A[MxK] @ B[KxNd], row-major. If DOT_C>0, also computes
// a_src[n,h] = sum_c C[n, h*DOT_C+c]*att_src[h,c] (ditto dst) -- each block's
// 64-column tile maps to whole head(s), so writes are exclusive per (n,h).
#define BM 64
#define BN 64
#define BK 16
template <int DOT_C>
__global__ __launch_bounds__(256) void sgemm_kernel(
    const float* __restrict__ A, const float* __restrict__ B,
    float* __restrict__ C, int M, int K, int Nd,
    const float* __restrict__ att_src, const float* __restrict__ att_dst) {
    __shared__ float As[BK][BM + 4];
    __shared__ float Bs[BK][BN];
    __shared__ float sAs[BN], sAd[BN];
    int tid = threadIdx.x;
    int block_m = blockIdx.y * BM;
    int block_n = blockIdx.x * BN;
    int tr = tid >> 4, tc = tid & 15;

    if (DOT_C > 0 && tid < BN) {
        sAs[tid] = att_src[block_n + tid];   // flat [H*C] layout
        sAd[tid] = att_dst[block_n + tid];
    }

    float a_reg[4], b_reg[4];
    float acc[4][4] = {};

    // prologue: tile 0
#pragma unroll
    for (int i = 0; i < 4; i++) {
        int idx = tid + i * 256;
        int m = idx / BK, kk = idx % BK;
        int row = block_m + m;
        a_reg[i] = (row < M) ? A[(size_t)row * K + kk] : 0.f;
    }
#pragma unroll
    for (int i = 0; i < 4; i++) {
        int idx = tid + i * 256;
        int kk = idx / BN, nn = idx % BN;
        b_reg[i] = B[(size_t)kk * Nd + block_n + nn];
    }
#pragma unroll
    for (int i = 0; i < 4; i++) {
        int idx = tid + i * 256;
        As[idx % BK][idx / BK] = a_reg[i];
    }
#pragma unroll
    for (int i = 0; i < 4; i++) {
        int idx = tid + i * 256;
        Bs[idx / BN][idx % BN] = b_reg[i];
    }
    __syncthreads();

    for (int k0 = BK; k0 < K; k0 += BK) {
        // prefetch next tile into registers
#pragma unroll
        for (int i = 0; i < 4; i++) {
            int idx = tid + i * 256;
            int m = idx / BK, kk = idx % BK;
            int row = block_m + m;
            a_reg[i] = (row < M) ? A[(size_t)row * K + k0 + kk] : 0.f;
        }
#pragma unroll
        for (int i = 0; i < 4; i++) {
            int idx = tid + i * 256;
            int kk = idx / BN, nn = idx % BN;
            b_reg[i] = B[(size_t)(k0 + kk) * Nd + block_n + nn];
        }
        // compute current tile from smem
#pragma unroll
        for (int kk = 0; kk < BK; kk++) {
            float4 a4 = *(const float4*)&As[kk][tr * 4];
            float4 b4 = *(const float4*)&Bs[kk][tc * 4];
            float av[4] = {a4.x, a4.y, a4.z, a4.w};
            float bv[4] = {b4.x, b4.y, b4.z, b4.w};
#pragma unroll
            for (int i = 0; i < 4; i++)
#pragma unroll
                for (int j = 0; j < 4; j++) acc[i][j] += av[i] * bv[j];
        }
        __syncthreads();
#pragma unroll
        for (int i = 0; i < 4; i++) {
            int idx = tid + i * 256;
            As[idx % BK][idx / BK] = a_reg[i];
        }
#pragma unroll
        for (int i = 0; i < 4; i++) {
            int idx = tid + i * 256;
            Bs[idx / BN][idx % BN] = b_reg[i];
        }
        __syncthreads();
    }
    // last tile
#pragma unroll
    for (int kk = 0; kk < BK; kk++) {
        float4 a4 = *(const float4*)&As[kk][tr * 4];
        float4 b4 = *(const float4*)&Bs[kk][tc * 4];
        float av[4] = {a4.x, a4.y, a4.z, a4.w};
        float bv[4] = {b4.x, b4.y, b4.z, b4.w};
#pragma unroll
        for (int i = 0; i < 4; i++)
#pragma unroll
            for (int j = 0; j < 4; j++) acc[i][j] += av[i] * bv[j];
    }

#pragma unroll
    for (int i = 0; i < 4; i++) {
        int row = block_m + tr * 4 + i;
        if (row < M) {
            float4 v = make_float4(acc[i][0], acc[i][1], acc[i][2], acc[i][3]);
            *(float4*)&C[(size_t)row * Nd + block_n + tc * 4] = v;
        }
    }

    if (DOT_C > 0) {
        const int G = DOT_C / 4;   // threads (tc) per head group: 16 or 8
        int lane = tid & 31;
#pragma unroll
        for (int i = 0; i < 4; i++) {
            float ps = 0.f, pd = 0.f;
#pragma unroll
            for (int j = 0; j < 4; j++) {
                ps += acc[i][j] * sAs[tc * 4 + j];
                pd += acc[i][j] * sAd[tc * 4 + j];
            }
#pragma unroll
            for (int off = G / 2; off; off >>= 1) {
                ps += __shfl_xor_sync(0xffffffff, ps, off);
                pd += __shfl_xor_sync(0xffffffff, pd, off);
            }
            if ((lane % G) == 0) {
                int row = block_m + tr * 4 + i;
                int head = (block_n + tc * 4) / DOT_C;
                if (row < M) {
                    g_asrc[row * 4 + head] = ps;
                    g_adst[row * 4 + head] = pd;
                }
            }
        }
    }
}

// ---------------- per-edge exp(leaky_relu(logit)), written dst-sorted ----------------
__device__ __forceinline__ float lrelu(float v) { return v > 0.f ? v : 0.2f * v; }

template <bool WRITE_EDGE_ORDER>
__global__ void edge_alpha_kernel(const int* __restrict__ ei) {
    int e = blockIdx.x * blockDim.x + threadIdx.x;
    if (e >= EE) return;
    int s = ei[e];
    int d = ei[EE + e];
    float4 as = *(const float4*)&g_asrc[s * 4];
    float4 ad = *(const float4*)&g_adst[d * 4];
    float4 al;
    al.x = __expf(lrelu(as.x + ad.x));
    al.y = __expf(lrelu(as.y + ad.y));
    al.z = __expf(lrelu(as.z + ad.z));
    al.w = __expf(lrelu(as.w + ad.w));
    *(float4*)&g_alpha_s[(size_t)g_pos[e] * 4] = al;
    if (WRITE_EDGE_ORDER) *(float4*)&g_alpha[(size_t)e * 4] = al;
}

// ---------------- softmax-sum + aggregate + head-mean + bias: warp per node ----------------
template <int C, bool WRITE_STATS>
__global__ void aggregate_kernel(const float* __restrict__ xl,
                                 const float* __restrict__ bias,
                                 float* __restrict__ out) {
    const int CH = HH * C;
    const int V = CH / 32;   // floats per lane per row
    int warp = (blockIdx.x * blockDim.x + threadIdx.x) >> 5;
    int lane = threadIdx.x & 31;
    if (warp >= NN) return;
    int start = g_rowptr[warp], end = g_rowptr[warp + 1];

    float s[4] = {0.f, 0.f, 0.f, 0.f};
    for (int i = start + lane; i < end; i += 32) {
        float4 a = *(const float4*)&g_alpha_s[(size_t)i * 4];
        s[0] += a.x; s[1] += a.y; s[2] += a.z; s[3] += a.w;
    }
#pragma unroll
    for (int off = 16; off; off >>= 1)
#pragma unroll
        for (int h = 0; h < 4; h++)
            s[h] += __shfl_xor_sync(0xffffffff, s[h], off);

    if (WRITE_STATS && lane < 4)
        g_nodeR[warp * 4 + lane] = 1.f / (s[lane] + 1e-16f);

    int myh = lane >> 3;
    float myR = 1.f / (s[myh] + 1e-16f);

    float acc[V];
#pragma unroll
    for (int j = 0; j < V; j++) acc[j] = 0.f;

    int i = start;
    for (; i + 3 < end; i += 4) {
        int sn0 = g_srcs[i], sn1 = g_srcs[i + 1], sn2 = g_srcs[i + 2], sn3 = g_srcs[i + 3];
        float al0 = g_alpha_s[(size_t)i * 4 + myh] * myR;
        float al1 = g_alpha_s[(size_t)(i + 1) * 4 + myh] * myR;
        float al2 = g_alpha_s[(size_t)(i + 2) * 4 + myh] * myR;
        float al3 = g_alpha_s[(size_t)(i + 3) * 4 + myh] * myR;
        const float4* p0 = (const float4*)(xl + (size_t)sn0 * CH + lane * V);
        const float4* p1 = (const float4*)(xl + (size_t)sn1 * CH + lane * V);
        const float4* p2 = (const float4*)(xl + (size_t)sn2 * CH + lane * V);
        const float4* p3 = (const float4*)(xl + (size_t)sn3 * CH + lane * V);
#pragma unroll
        for (int j4 = 0; j4 < V / 4; j4++) {
            float4 v0 = p0[j4], v1 = p1[j4], v2 = p2[j4], v3 = p3[j4];
            acc[j4 * 4 + 0] += al0 * v0.x + al1 * v1.x + al2 * v2.x + al3 * v3.x;
            acc[j4 * 4 + 1] += al0 * v0.y + al1 * v1.y + al2 * v2.y + al3 * v3.y;
            acc[j4 * 4 + 2] += al0 * v0.z + al1 * v1.z + al2 * v2.z + al3 * v3.z;
            acc[j4 * 4 + 3] += al0 * v0.w + al1 * v1.w + al2 * v2.w + al3 * v3.w;
        }
    }
    for (; i < end; i++) {
        int sn0 = g_srcs[i];
        float al0 = g_alpha_s[(size_t)i * 4 + myh] * myR;
        const float4* p0 = (const float4*)(xl + (size_t)sn0 * CH + lane * V);
#pragma unroll
        for (int j4 = 0; j4 < V / 4; j4++) {
            float4 v0 = p0[j4];
            acc[j4 * 4 + 0] += al0 * v0.x;
            acc[j4 * 4 + 1] += al0 * v0.y;
            acc[j4 * 4 + 2] += al0 * v0.z;
            acc[j4 * 4 + 3] += al0 * v0.w;
        }
    }
#pragma unroll
    for (int j = 0; j < V; j++) {
        acc[j] += __shfl_xor_sync(0xffffffff, acc[j], 8);
        acc[j] += __shfl_xor_sync(0xffffffff, acc[j], 16);
    }
    if (lane < 8) {
#pragma unroll
        for (int j = 0; j < V; j++)
            out[(size_t)warp * C + lane * V + j] = acc[j] * 0.25f + bias[lane * V + j];
    }
}

// ---------------- node projections P[n] = out2[n] @ [mW1_src | mW1_dst] ----------------
__global__ __launch_bounds__(256) void build_P_kernel(const float* __restrict__ out2,
                                                      const float* __restrict__ mW1) {
    __shared__ float sWp[32 * 128];
    int tid = threadIdx.x;
    for (int idx = tid; idx < 32 * 128; idx += 256) {
        int k = idx >> 7, j = idx & 127;
        sWp[idx] = (j < 64) ? mW1[k * 64 + j] : mW1[(36 + k) * 64 + (j - 64)];
    }
    __syncthreads();
    int node = (blockIdx.x * 256 + tid) >> 5;
    int lane = tid & 31;
    if (node >= NN) return;
    float own = out2[(size_t)node * 32 + lane];
    float a0 = 0.f, a1 = 0.f, a2 = 0.f, a3 = 0.f;
#pragma unroll
    for (int k = 0; k < 32; k++) {
        float f = __shfl_sync(0xffffffff, own, k);
        a0 += f * sWp[k * 128 + lane];
        a1 += f * sWp[k * 128 + lane + 32];
        a2 += f * sWp[k * 128 + lane + 64];
        a3 += f * sWp[k * 128 + lane + 96];
    }
    float* Pr = &g_P[(size_t)node * 128];
    Pr[lane]      = a0;
    Pr[lane + 32] = a1;
    Pr[lane + 64] = a2;
    Pr[lane + 96] = a3;
}

// ---------------- edge MLP finish (alpha normalization fused): warp per edge ----------------
__global__ __launch_bounds__(256) void edge_mlp_kernel(
    const int* __restrict__ ei,
    const float* __restrict__ mW1, const float* __restrict__ mb1,
    const float* __restrict__ mW2, const float* __restrict__ mb2,
    float* __restrict__ edge_out) {
    __shared__ float sWa[4 * 64];   // mW1 rows 32..35 (alpha rows)
    __shared__ float sW2[128];      // mW2 [64,2]
    __shared__ float sb1[64];
    int tid = threadIdx.x;
    sWa[tid] = mW1[(32 + (tid >> 6)) * 64 + (tid & 63)];
    if (tid < 128) sW2[tid] = mW2[tid];
    if (tid < 64)  sb1[tid] = mb1[tid];
    __syncthreads();

    int e = (blockIdx.x * 256 + tid) >> 5;
    int lane = tid & 31;
    if (e >= EE) return;
    int s = ei[e], d = ei[EE + e];
    float4 ex = *(const float4*)&g_alpha[(size_t)e * 4];
    float4 R  = *(const float4*)&g_nodeR[d * 4];
    float4 a;
    a.x = ex.x * R.x;
    a.y = ex.y * R.y;
    a.z = ex.z * R.z;
    a.w = ex.w * R.w;

    const float* Ps = &g_P[(size_t)s * 128];
    const float* Pd = &g_P[(size_t)d * 128 + 64];
    int c0 = lane, c1 = lane + 32;

    float h0 = Ps[c0] + Pd[c0] + sb1[c0]
             + a.x * sWa[c0] + a.y * sWa[64 + c0] + a.z * sWa[128 + c0] + a.w * sWa[192 + c0];
    float h1 = Ps[c1] + Pd[c1] + sb1[c1]
             + a.x * sWa[c1] + a.y * sWa[64 + c1] + a.z * sWa[128 + c1] + a.w * sWa[192 + c1];
    h0 = fmaxf(h0, 0.f);
    h1 = fmaxf(h1, 0.f);
    float s0 = h0 * sW2[c0 * 2 + 0] + h1 * sW2[c1 * 2 + 0];
    float s1 = h0 * sW2[c0 * 2 + 1] + h1 * sW2[c1 * 2 + 1];
#pragma unroll
    for (int off = 16; off; off >>= 1) {
        s0 += __shfl_xor_sync(0xffffffff, s0, off);
        s1 += __shfl_xor_sync(0xffffffff, s1, off);
    }
    if (lane == 0) {
        edge_out[(size_t)e * 2 + 0] = s0 + mb2[0];
        edge_out[(size_t)e * 2 + 1] = s1 + mb2[1];
    }
}

// ---------------- launch ----------------
extern "C" void kernel_launch(void* const* d_in, const int* in_sizes, int n_in,
                              void* d_out, int out_size) {
    const float* x        = (const float*)d_in[0];
    const int*   ei       = (const int*)d_in[1];
    const float* W1       = (const float*)d_in[4];
    const float* att1_src = (const float*)d_in[5];
    const float* att1_dst = (const float*)d_in[6];
    const float* b1       = (const float*)d_in[7];
    const float* W3       = (const float*)d_in[8];
    const float* att3_src = (const float*)d_in[9];
    const float* att3_dst = (const float*)d_in[10];
    const float* b3       = (const float*)d_in[11];
    const float* mW1      = (const float*)d_in[12];
    const float* mb1      = (const float*)d_in[13];
    const float* mW2      = (const float*)d_in[14];
    const float* mb2      = (const float*)d_in[15];

    float* out2     = (float*)d_out;          // [N, 32]
    float* edge_out = out2 + (size_t)NN * 32; // [E, 2]

    // 0: sgemm1 + attention dots fused
    {
        dim3 grid(256 / BN, (NN + BM - 1) / BM);
        sgemm_kernel<64><<<grid, 256>>>(x, W1, g_xl, NN, 128, 256, att1_src, att1_dst);
    }
    zero_counts_kernel<<<(NN + 255) / 256, 256>>>();   // 1
    hist_kernel<<<(EE + 255) / 256, 256>>>(ei);        // 2
    scan_kernel<<<1, 1024>>>();                        // 3  <- profiled slot
    scatter_kernel<<<(EE + 255) / 256, 256>>>(ei);     // 4

    // Layer 1
    edge_alpha_kernel<false><<<(EE + 255) / 256, 256>>>(ei);                            // 5
    aggregate_kernel<64, false><<<(NN * 32 + 255) / 256, 256>>>(g_xl, b1, g_out1);      // 6

    // Layer 2 (sgemm + dots fused)
    {
        dim3 grid(128 / BN, (NN + BM - 1) / BM);
        sgemm_kernel<32><<<grid, 256>>>(g_out1, W3, g_xl, NN, 64, 128, att3_src, att3_dst); // 7
    }
    edge_alpha_kernel<true><<<(EE + 255) / 256, 256>>>(ei);                             // 8
    aggregate_kernel<32, true><<<(NN * 32 + 255) / 256, 256>>>(g_xl, b3, out2);         // 9

    // Edge outputs
    build_P_kernel<<<(NN * 32 + 255) / 256, 256>>>(out2, mW1);                          // 10
    edge_mlp_kernel<<<(EE * 32 + 255) / 256, 256>>>(ei, mW1, mb1, mW2, mb2, edge_out);  // 11
}

// round 9
// speedup vs baseline: 1.0193x; 1.0193x over previous
#include <cuda_runtime.h>

#define NN 50000
#define EE 800000
#define HH 4

// ---------------- scratch (static __device__, no allocations) ----------------
__device__ __align__(16) float g_xl[NN * 256];      // xl1 [N,256] then xl2 [N,128]
__device__ __align__(16) float g_out1[NN * 64];     // layer-1 output [N,64]
__device__ __align__(16) float g_P[NN * 128];       // node projections for edge MLP
__device__ __align__(16) float g_alpha[EE * 4];     // exp(logit), edge order (layer 2 only)
__device__ __align__(16) float g_alpha_s[EE * 4];   // exp(logit), dst-sorted order
__device__ __align__(16) float g_asrc[NN * 4];
__device__ __align__(16) float g_adst[NN * 4];
__device__ __align__(16) float g_nodeR[NN * 4];     // per-node 1/(sum+eps) (layer 2)
__device__ int g_deg[NN];
__device__ int g_cursor[NN];
__device__ int g_rowptr[NN + 1];
__device__ int g_pos[EE];             // edge id -> sorted position
__device__ int g_srcs[EE];            // src node per sorted edge

// ---------------- CSR build ----------------
__global__ void zero_counts_kernel() {
    int i = blockIdx.x * blockDim.x + threadIdx.x;
    if (i < NN) { g_deg[i] = 0; g_cursor[i] = 0; }
}

__global__ void hist_kernel(const int* __restrict__ ei) {
    int e = blockIdx.x * blockDim.x + threadIdx.x;
    if (e >= EE) return;
    atomicAdd(&g_deg[ei[EE + e]], 1);
}

__global__ void scan_kernel() {
    __shared__ int sh[1024];
    int t = threadIdx.x;
    const int chunk = (NN + 1023) / 1024;
    int beg = t * chunk;
    int end = beg + chunk; if (end > NN) end = NN; if (beg > NN) beg = NN;
    int s = 0;
    for (int i = beg; i < end; i++) s += g_deg[i];
    sh[t] = s;
    __syncthreads();
    for (int off = 1; off < 1024; off <<= 1) {
        int v = (t >= off) ? sh[t - off] : 0;
        __syncthreads();
        sh[t] += v;
        __syncthreads();
    }
    int run = (t > 0) ? sh[t - 1] : 0;
    for (int i = beg; i < end; i++) { g_rowptr[i] = run; run += g_deg[i]; }
    if (t == 0) g_rowptr[NN] = sh[1023];
}

__global__ void scatter_kernel(const int* __restrict__ ei) {
    int e = blockIdx.x * blockDim.x + threadIdx.x;
    if (e >= EE) return;
    int d = ei[EE + e];
    int pos = g_rowptr[d] + atomicAdd(&g_cursor[d], 1);
    g_pos[e] = pos;
    g_srcs[pos] = ei[e];
}

// ---------------- SGEMM: C[MxNd] = A[MxK] @ B[KxNd], row-major (R3 version) ----------------
#define BM 64
#define BN 64
#define BK 16
__global__ __launch_bounds__(256) void sgemm_kernel(
    const float* __restrict__ A, const float* __restrict__ B,
    float* __restrict__ C, int M, int K, int Nd) {
    __shared__ float As[BK][BM + 4];
    __shared__ float Bs[BK][BN];
    int tid = threadIdx.x;
    int block_m = blockIdx.y * BM;
    int block_n = blockIdx.x * BN;
    int tr = tid >> 4, tc = tid & 15;
    float acc[4][4] = {};
    for (int k0 = 0; k0 < K; k0 += BK) {
#pragma unroll
        for (int i = 0; i < (BM * BK) / 256; i++) {
            int idx = tid + i * 256;
            int m = idx / BK, kk = idx % BK;
            int row = block_m + m;
            As[kk][m] = (row < M) ? A[(size_t)row * K + k0 + kk] : 0.f;
        }
#pragma unroll
        for (int i = 0; i < (BK * BN) / 256; i++) {
            int idx = tid + i * 256;
            int kk = idx / BN, nn = idx % BN;
            Bs[kk][nn] = B[(size_t)(k0 + kk) * Nd + block_n + nn];
        }
        __syncthreads();
#pragma unroll
        for (int kk = 0; kk < BK; kk++) {
            float4 a4 = *(const float4*)&As[kk][tr * 4];
            float4 b4 = *(const float4*)&Bs[kk][tc * 4];
            float av[4] = {a4.x, a4.y, a4.z, a4.w};
            float bv[4] = {b4.x, b4.y, b4.z, b4.w};
#pragma unroll
            for (int i = 0; i < 4; i++)
#pragma unroll
                for (int j = 0; j < 4; j++) acc[i][j] += av[i] * bv[j];
        }
        __syncthreads();
    }
#pragma unroll
    for (int i = 0; i < 4; i++) {
        int row = block_m + tr * 4 + i;
        if (row < M) {
            float4 v = make_float4(acc[i][0], acc[i][1], acc[i][2], acc[i][3]);
            *(float4*)&C[(size_t)row * Nd + block_n + tc * 4] = v;
        }
    }
}

// ---------------- attention dot products: warp per node ----------------
template <int C>
__global__ void att_dot_kernel(const float* __restrict__ xl,
                               const float* __restrict__ att_src,
                               const float* __restrict__ att_dst) {
    const int CH = HH * C;
    const int V = CH / 32;
    int warp = (blockIdx.x * blockDim.x + threadIdx.x) >> 5;
    int lane = threadIdx.x & 31;
    if (warp >= NN) return;
    const float* xr = xl + (size_t)warp * CH + lane * V;
    int h = (lane * V) / C;
    int cbase = (lane * V) % C;
    float ps = 0.f, pd = 0.f;
#pragma unroll
    for (int j = 0; j < V; j++) {
        float v = xr[j];
        ps += v * att_src[h * C + cbase + j];
        pd += v * att_dst[h * C + cbase + j];
    }
#pragma unroll
    for (int off = 4; off; off >>= 1) {
        ps += __shfl_xor_sync(0xffffffff, ps, off);
        pd += __shfl_xor_sync(0xffffffff, pd, off);
    }
    if ((lane & 7) == 0) {
        g_asrc[warp * 4 + (lane >> 3)] = ps;
        g_adst[warp * 4 + (lane >> 3)] = pd;
    }
}

// ---------------- per-edge exp(leaky_relu(logit)), written dst-sorted ----------------
__device__ __forceinline__ float lrelu(float v) { return v > 0.f ? v : 0.2f * v; }

template <bool WRITE_EDGE_ORDER>
__global__ void edge_alpha_kernel(const int* __restrict__ ei) {
    int e = blockIdx.x * blockDim.x + threadIdx.x;
    if (e >= EE) return;
    int s = ei[e];
    int d = ei[EE + e];
    float4 as = *(const float4*)&g_asrc[s * 4];
    float4 ad = *(const float4*)&g_adst[d * 4];
    float4 al;
    al.x = __expf(lrelu(as.x + ad.x));
    al.y = __expf(lrelu(as.y + ad.y));
    al.z = __expf(lrelu(as.z + ad.z));
    al.w = __expf(lrelu(as.w + ad.w));
    *(float4*)&g_alpha_s[(size_t)g_pos[e] * 4] = al;
    if (WRITE_EDGE_ORDER) *(float4*)&g_alpha[(size_t)e * 4] = al;
}

// ---------------- softmax-sum + aggregate + head-mean + bias: warp per node ----------------
template <int C, bool WRITE_STATS>
__global__ void aggregate_kernel(const float* __restrict__ xl,
                                 const float* __restrict__ bias,
                                 float* __restrict__ out) {
    const int CH = HH * C;
    const int V = CH / 32;
    int warp = (blockIdx.x * blockDim.x + threadIdx.x) >> 5;
    int lane = threadIdx.x & 31;
    if (warp >= NN) return;
    int start = g_rowptr[warp], end = g_rowptr[warp + 1];

    float s[4] = {0.f, 0.f, 0.f, 0.f};
    for (int i = start + lane; i < end; i += 32) {
        float4 a = *(const float4*)&g_alpha_s[(size_t)i * 4];
        s[0] += a.x; s[1] += a.y; s[2] += a.z; s[3] += a.w;
    }
#pragma unroll
    for (int off = 16; off; off >>= 1)
#pragma unroll
        for (int h = 0; h < 4; h++)
            s[h] += __shfl_xor_sync(0xffffffff, s[h], off);

    if (WRITE_STATS && lane < 4)
        g_nodeR[warp * 4 + lane] = 1.f / (s[lane] + 1e-16f);

    int myh = lane >> 3;
    float myR = 1.f / (s[myh] + 1e-16f);

    float acc[V];
#pragma unroll
    for (int j = 0; j < V; j++) acc[j] = 0.f;

    int i = start;
    for (; i + 3 < end; i += 4) {
        int sn0 = g_srcs[i], sn1 = g_srcs[i + 1], sn2 = g_srcs[i + 2], sn3 = g_srcs[i + 3];
        float al0 = g_alpha_s[(size_t)i * 4 + myh] * myR;
        float al1 = g_alpha_s[(size_t)(i + 1) * 4 + myh] * myR;
        float al2 = g_alpha_s[(size_t)(i + 2) * 4 + myh] * myR;
        float al3 = g_alpha_s[(size_t)(i + 3) * 4 + myh] * myR;
        const float4* p0 = (const float4*)(xl + (size_t)sn0 * CH + lane * V);
        const float4* p1 = (const float4*)(xl + (size_t)sn1 * CH + lane * V);
        const float4* p2 = (const float4*)(xl + (size_t)sn2 * CH + lane * V);
        const float4* p3 = (const float4*)(xl + (size_t)sn3 * CH + lane * V);
#pragma unroll
        for (int j4 = 0; j4 < V / 4; j4++) {
            float4 v0 = p0[j4], v1 = p1[j4], v2 = p2[j4], v3 = p3[j4];
            acc[j4 * 4 + 0] += al0 * v0.x + al1 * v1.x + al2 * v2.x + al3 * v3.x;
            acc[j4 * 4 + 1] += al0 * v0.y + al1 * v1.y + al2 * v2.y + al3 * v3.y;
            acc[j4 * 4 + 2] += al0 * v0.z + al1 * v1.z + al2 * v2.z + al3 * v3.z;
            acc[j4 * 4 + 3] += al0 * v0.w + al1 * v1.w + al2 * v2.w + al3 * v3.w;
        }
    }
    for (; i < end; i++) {
        int sn0 = g_srcs[i];
        float al0 = g_alpha_s[(size_t)i * 4 + myh] * myR;
        const float4* p0 = (const float4*)(xl + (size_t)sn0 * CH + lane * V);
#pragma unroll
        for (int j4 = 0; j4 < V / 4; j4++) {
            float4 v0 = p0[j4];
            acc[j4 * 4 + 0] += al0 * v0.x;
            acc[j4 * 4 + 1] += al0 * v0.y;
            acc[j4 * 4 + 2] += al0 * v0.z;
            acc[j4 * 4 + 3] += al0 * v0.w;
        }
    }
#pragma unroll
    for (int j = 0; j < V; j++) {
        acc[j] += __shfl_xor_sync(0xffffffff, acc[j], 8);
        acc[j] += __shfl_xor_sync(0xffffffff, acc[j], 16);
    }
    if (lane < 8) {
#pragma unroll
        for (int j = 0; j < V; j++)
            out[(size_t)warp * C + lane * V + j] = acc[j] * 0.25f + bias[lane * V + j];
    }
}

// ---------------- node projections P[n] = out2[n] @ [mW1_src | mW1_dst] ----------------
__global__ __launch_bounds__(256) void build_P_kernel(const float* __restrict__ out2,
                                                      const float* __restrict__ mW1) {
    __shared__ float sWp[32 * 128];
    int tid = threadIdx.x;
    for (int idx = tid; idx < 32 * 128; idx += 256) {
        int k = idx >> 7, j = idx & 127;
        sWp[idx] = (j < 64) ? mW1[k * 64 + j] : mW1[(36 + k) * 64 + (j - 64)];
    }
    __syncthreads();
    int node = (blockIdx.x * 256 + tid) >> 5;
    int lane = tid & 31;
    if (node >= NN) return;
    float own = out2[(size_t)node * 32 + lane];
    float a0 = 0.f, a1 = 0.f, a2 = 0.f, a3 = 0.f;
#pragma unroll
    for (int k = 0; k < 32; k++) {
        float f = __shfl_sync(0xffffffff, own, k);
        a0 += f * sWp[k * 128 + lane];
        a1 += f * sWp[k * 128 + lane + 32];
        a2 += f * sWp[k * 128 + lane + 64];
        a3 += f * sWp[k * 128 + lane + 96];
    }
    float* Pr = &g_P[(size_t)node * 128];
    Pr[lane]      = a0;
    Pr[lane + 32] = a1;
    Pr[lane + 64] = a2;
    Pr[lane + 96] = a3;
}

// ---------------- edge MLP finish (alpha normalization fused): warp per edge ----------------
__global__ __launch_bounds__(256) void edge_mlp_kernel(
    const int* __restrict__ ei,
    const float* __restrict__ mW1, const float* __restrict__ mb1,
    const float* __restrict__ mW2, const float* __restrict__ mb2,
    float* __restrict__ edge_out) {
    __shared__ float sWa[4 * 64];
    __shared__ float sW2[128];
    __shared__ float sb1[64];
    int tid = threadIdx.x;
    sWa[tid] = mW1[(32 + (tid >> 6)) * 64 + (tid & 63)];
    if (tid < 128) sW2[tid] = mW2[tid];
    if (tid < 64)  sb1[tid] = mb1[tid];
    __syncthreads();

    int e = (blockIdx.x * 256 + tid) >> 5;
    int lane = tid & 31;
    if (e >= EE) return;
    int s = ei[e], d = ei[EE + e];
    float4 ex = *(const float4*)&g_alpha[(size_t)e * 4];
    float4 R  = *(const float4*)&g_nodeR[d * 4];
    float4 a;
    a.x = ex.x * R.x;
    a.y = ex.y * R.y;
    a.z = ex.z * R.z;
    a.w = ex.w * R.w;

    const float* Ps = &g_P[(size_t)s * 128];
    const float* Pd = &g_P[(size_t)d * 128 + 64];
    int c0 = lane, c1 = lane + 32;

    float h0 = Ps[c0] + Pd[c0] + sb1[c0]
             + a.x * sWa[c0] + a.y * sWa[64 + c0] + a.z * sWa[128 + c0] + a.w * sWa[192 + c0];
    float h1 = Ps[c1] + Pd[c1] + sb1[c1]
             + a.x * sWa[c1] + a.y * sWa[64 + c1] + a.z * sWa[128 + c1] + a.w * sWa[192 + c1];
    h0 = fmaxf(h0, 0.f);
    h1 = fmaxf(h1, 0.f);
    float s0 = h0 * sW2[c0 * 2 + 0] + h1 * sW2[c1 * 2 + 0];
    float s1 = h0 * sW2[c0 * 2 + 1] + h1 * sW2[c1 * 2 + 1];
#pragma unroll
    for (int off = 16; off; off >>= 1) {
        s0 += __shfl_xor_sync(0xffffffff, s0, off);
        s1 += __shfl_xor_sync(0xffffffff, s1, off);
    }
    if (lane == 0) {
        edge_out[(size_t)e * 2 + 0] = s0 + mb2[0];
        edge_out[(size_t)e * 2 + 1] = s1 + mb2[1];
    }
}

// ---------------- launch ----------------
extern "C" void kernel_launch(void* const* d_in, const int* in_sizes, int n_in,
                              void* d_out, int out_size) {
    const float* x        = (const float*)d_in[0];
    const int*   ei       = (const int*)d_in[1];
    const float* W1       = (const float*)d_in[4];
    const float* att1_src = (const float*)d_in[5];
    const float* att1_dst = (const float*)d_in[6];
    const float* b1       = (const float*)d_in[7];
    const float* W3       = (const float*)d_in[8];
    const float* att3_src = (const float*)d_in[9];
    const float* att3_dst = (const float*)d_in[10];
    const float* b3       = (const float*)d_in[11];
    const float* mW1      = (const float*)d_in[12];
    const float* mb1      = (const float*)d_in[13];
    const float* mW2      = (const float*)d_in[14];
    const float* mb2      = (const float*)d_in[15];

    float* out2     = (float*)d_out;          // [N, 32]
    float* edge_out = out2 + (size_t)NN * 32; // [E, 2]

    {
        dim3 grid(256 / BN, (NN + BM - 1) / BM);
        sgemm_kernel<<<grid, 256>>>(x, W1, g_xl, NN, 128, 256);                         // 0
    }
    zero_counts_kernel<<<(NN + 255) / 256, 256>>>();                                    // 1
    hist_kernel<<<(EE + 255) / 256, 256>>>(ei);                                         // 2
    att_dot_kernel<64><<<(NN * 32 + 255) / 256, 256>>>(g_xl, att1_src, att1_dst);       // 3 <- profiled
    scan_kernel<<<1, 1024>>>();                                                         // 4
    scatter_kernel<<<(EE + 255) / 256, 256>>>(ei);                                      // 5

    // Layer 1
    edge_alpha_kernel<false><<<(EE + 255) / 256, 256>>>(ei);                            // 6
    aggregate_kernel<64, false><<<(NN * 32 + 255) / 256, 256>>>(g_xl, b1, g_out1);      // 7

    // Layer 2
    {
        dim3 grid(128 / BN, (NN + BM - 1) / BM);
        sgemm_kernel<<<grid, 256>>>(g_out1, W3, g_xl, NN, 64, 128);                     // 8
    }
    att_dot_kernel<32><<<(NN * 32 + 255) / 256, 256>>>(g_xl, att3_src, att3_dst);       // 9
    edge_alpha_kernel<true><<<(EE + 255) / 256, 256>>>(ei);                             // 10
    aggregate_kernel<32, true><<<(NN * 32 + 255) / 256, 256>>>(g_xl, b3, out2);         // 11

    // Edge outputs
    build_P_kernel<<<(NN * 32 + 255) / 256, 256>>>(out2, mW1);                          // 12
    edge_mlp_kernel<<<(EE * 32 + 255) / 256, 256>>>(ei, mW1, mb1, mW2, mb2, edge_out);  // 13
}

// round 10
// speedup vs baseline: 1.2943x; 1.2697x over previous
#include <cuda_runtime.h>

#define NN 50000
#define EE 800000
#define HH 4

// ---------------- scratch (static __device__, no allocations) ----------------
__device__ __align__(16) float g_xl[NN * 256];      // xl1 [N,256] then xl2 [N,128]
__device__ __align__(16) float g_out1[NN * 64];     // layer-1 output [N,64]
__device__ __align__(16) float g_P[NN * 128];       // node projections for edge MLP
__device__ __align__(16) float g_alpha[EE * 4];     // exp(logit), edge order (layer 2 only)
__device__ __align__(16) float g_alpha_s[EE * 4];   // exp(logit), dst-sorted order
__device__ __align__(16) float g_asrc[NN * 4];
__device__ __align__(16) float g_adst[NN * 4];
__device__ __align__(16) float g_nodeR[NN * 4];     // per-node 1/(sum+eps) (layer 2)
__device__ int g_deg[NN];
__device__ int g_cursor[NN];
__device__ int g_rowptr[NN + 1];
__device__ int g_pos[EE];             // edge id -> sorted position
__device__ int g_srcs[EE];            // src node per sorted edge

// ---------------- CSR build ----------------
__global__ void zero_counts_kernel() {
    int i = blockIdx.x * blockDim.x + threadIdx.x;
    if (i < NN) { g_deg[i] = 0; g_cursor[i] = 0; }
}

__global__ void hist_kernel(const int* __restrict__ ei) {
    int e = blockIdx.x * blockDim.x + threadIdx.x;
    if (e >= EE) return;
    atomicAdd(&g_deg[ei[EE + e]], 1);
}

__global__ void scan_kernel() {
    __shared__ int sh[1024];
    int t = threadIdx.x;
    const int chunk = (NN + 1023) / 1024;
    int beg = t * chunk;
    int end = beg + chunk; if (end > NN) end = NN; if (beg > NN) beg = NN;
    int s = 0;
    for (int i = beg; i < end; i++) s += g_deg[i];
    sh[t] = s;
    __syncthreads();
    for (int off = 1; off < 1024; off <<= 1) {
        int v = (t >= off) ? sh[t - off] : 0;
        __syncthreads();
        sh[t] += v;
        __syncthreads();
    }
    int run = (t > 0) ? sh[t - 1] : 0;
    for (int i = beg; i < end; i++) { g_rowptr[i] = run; run += g_deg[i]; }
    if (t == 0) g_rowptr[NN] = sh[1023];
}

__global__ void scatter_kernel(const int* __restrict__ ei) {
    int e = blockIdx.x * blockDim.x + threadIdx.x;
    if (e >= EE) return;
    int d = ei[EE + e];
    int pos = g_rowptr[d] + atomicAdd(&g_cursor[d], 1);
    g_pos[e] = pos;
    g_srcs[pos] = ei[e];
}

// ---------------- SGEMM: C[MxNd] = A[MxK] @ B[KxNd], row-major ----------------
#define BM 64
#define BN 64
#define BK 16
__global__ __launch_bounds__(256) void sgemm_kernel(
    const float* __restrict__ A, const float* __restrict__ B,
    float* __restrict__ C, int M, int K, int Nd) {
    __shared__ float As[BK][BM + 4];
    __shared__ float Bs[BK][BN];
    int tid = threadIdx.x;
    int block_m = blockIdx.y * BM;
    int block_n = blockIdx.x * BN;
    int tr = tid >> 4, tc = tid & 15;
    float acc[4][4] = {};
    for (int k0 = 0; k0 < K; k0 += BK) {
#pragma unroll
        for (int i = 0; i < (BM * BK) / 256; i++) {
            int idx = tid + i * 256;
            int m = idx / BK, kk = idx % BK;
            int row = block_m + m;
            As[kk][m] = (row < M) ? A[(size_t)row * K + k0 + kk] : 0.f;
        }
#pragma unroll
        for (int i = 0; i < (BK * BN) / 256; i++) {
            int idx = tid + i * 256;
            int kk = idx / BN, nn = idx % BN;
            Bs[kk][nn] = B[(size_t)(k0 + kk) * Nd + block_n + nn];
        }
        __syncthreads();
#pragma unroll
        for (int kk = 0; kk < BK; kk++) {
            float4 a4 = *(const float4*)&As[kk][tr * 4];
            float4 b4 = *(const float4*)&Bs[kk][tc * 4];
            float av[4] = {a4.x, a4.y, a4.z, a4.w};
            float bv[4] = {b4.x, b4.y, b4.z, b4.w};
#pragma unroll
            for (int i = 0; i < 4; i++)
#pragma unroll
                for (int j = 0; j < 4; j++) acc[i][j] += av[i] * bv[j];
        }
        __syncthreads();
    }
#pragma unroll
    for (int i = 0; i < 4; i++) {
        int row = block_m + tr * 4 + i;
        if (row < M) {
            float4 v = make_float4(acc[i][0], acc[i][1], acc[i][2], acc[i][3]);
            *(float4*)&C[(size_t)row * Nd + block_n + tc * 4] = v;
        }
    }
}

// ---------------- attention dot products: warp per node ----------------
template <int C>
__global__ void att_dot_kernel(const float* __restrict__ xl,
                               const float* __restrict__ att_src,
                               const float* __restrict__ att_dst) {
    const int CH = HH * C;
    const int V = CH / 32;
    int warp = (blockIdx.x * blockDim.x + threadIdx.x) >> 5;
    int lane = threadIdx.x & 31;
    if (warp >= NN) return;
    const float* xr = xl + (size_t)warp * CH + lane * V;
    int h = (lane * V) / C;
    int cbase = (lane * V) % C;
    float ps = 0.f, pd = 0.f;
#pragma unroll
    for (int j = 0; j < V; j++) {
        float v = xr[j];
        ps += v * att_src[h * C + cbase + j];
        pd += v * att_dst[h * C + cbase + j];
    }
#pragma unroll
    for (int off = 4; off; off >>= 1) {
        ps += __shfl_xor_sync(0xffffffff, ps, off);
        pd += __shfl_xor_sync(0xffffffff, pd, off);
    }
    if ((lane & 7) == 0) {
        g_asrc[warp * 4 + (lane >> 3)] = ps;
        g_adst[warp * 4 + (lane >> 3)] = pd;
    }
}

// ---------------- per-edge exp(leaky_relu(logit)), written dst-sorted ----------------
__device__ __forceinline__ float lrelu(float v) { return v > 0.f ? v : 0.2f * v; }

template <bool WRITE_EDGE_ORDER>
__global__ void edge_alpha_kernel(const int* __restrict__ ei) {
    int e = blockIdx.x * blockDim.x + threadIdx.x;
    if (e >= EE) return;
    int s = ei[e];
    int d = ei[EE + e];
    float4 as = *(const float4*)&g_asrc[s * 4];
    float4 ad = *(const float4*)&g_adst[d * 4];
    float4 al;
    al.x = __expf(lrelu(as.x + ad.x));
    al.y = __expf(lrelu(as.y + ad.y));
    al.z = __expf(lrelu(as.z + ad.z));
    al.w = __expf(lrelu(as.w + ad.w));
    *(float4*)&g_alpha_s[(size_t)g_pos[e] * 4] = al;
    if (WRITE_EDGE_ORDER) *(float4*)&g_alpha[(size_t)e * 4] = al;
}

// ---------------- aggregate v2: 4 warps per node, 2 nodes per 256-thread block ----------------
// Phase 1: alpha-sum (thread-parallel, 128 threads per node)
// Phase 2: gather, warp w handles edges start+w, start+w+4, ... (partials in regs)
// Phase 3: smem cross-warp reduce + head-mean + bias
template <int C, bool WRITE_STATS>
__global__ __launch_bounds__(256) void aggregate2_kernel(const float* __restrict__ xl,
                                                         const float* __restrict__ bias,
                                                         float* __restrict__ out) {
    const int CH = HH * C;
    const int V = CH / 32;           // floats per lane (8 for C=64, 4 for C=32)
    __shared__ float sS[2][4][4];    // [node][warp][head] alpha partial sums
    __shared__ float sAcc[2][4][HH * C];  // [node][warp][channel]

    int tid = threadIdx.x;
    int wid = tid >> 5;              // 0..7
    int lane = tid & 31;
    int local = wid >> 2;            // node slot within block (0/1)
    int w = wid & 3;                 // warp within node (0..3)
    int node = blockIdx.x * 2 + local;   // NN even -> always valid

    int start = g_rowptr[node], end = g_rowptr[node + 1];

    // ---- Phase 1: alpha sums (128 threads per node, each reads float4) ----
    float s0 = 0.f, s1 = 0.f, s2 = 0.f, s3 = 0.f;
    for (int i = start + (w * 32 + lane); i < end; i += 128) {
        float4 a = *(const float4*)&g_alpha_s[(size_t)i * 4];
        s0 += a.x; s1 += a.y; s2 += a.z; s3 += a.w;
    }
#pragma unroll
    for (int off = 16; off; off >>= 1) {
        s0 += __shfl_xor_sync(0xffffffff, s0, off);
        s1 += __shfl_xor_sync(0xffffffff, s1, off);
        s2 += __shfl_xor_sync(0xffffffff, s2, off);
        s3 += __shfl_xor_sync(0xffffffff, s3, off);
    }
    if (lane == 0) {
        sS[local][w][0] = s0; sS[local][w][1] = s1;
        sS[local][w][2] = s2; sS[local][w][3] = s3;
    }
    __syncthreads();

    int myh = lane >> 3;   // head for this lane's channels (V*lane spans within one head)
    float myR = 1.f / (sS[local][0][myh] + sS[local][1][myh] +
                       sS[local][2][myh] + sS[local][3][myh] + 1e-16f);
    if (WRITE_STATS && w == 0 && lane < 4) {
        g_nodeR[node * 4 + lane] = 1.f / (sS[local][0][lane] + sS[local][1][lane] +
                                          sS[local][2][lane] + sS[local][3][lane] + 1e-16f);
    }

    // ---- Phase 2: gather, warp-strided edges, x2 unroll ----
    float acc[V];
#pragma unroll
    for (int j = 0; j < V; j++) acc[j] = 0.f;

    int i = start + w;
    for (; i + 4 < end; i += 8) {
        int sn0 = g_srcs[i];
        int sn1 = g_srcs[i + 4];
        float al0 = g_alpha_s[(size_t)i * 4 + myh] * myR;
        float al1 = g_alpha_s[(size_t)(i + 4) * 4 + myh] * myR;
        const float4* p0 = (const float4*)(xl + (size_t)sn0 * CH + lane * V);
        const float4* p1 = (const float4*)(xl + (size_t)sn1 * CH + lane * V);
#pragma unroll
        for (int j4 = 0; j4 < V / 4; j4++) {
            float4 v0 = p0[j4], v1 = p1[j4];
            acc[j4 * 4 + 0] += al0 * v0.x + al1 * v1.x;
            acc[j4 * 4 + 1] += al0 * v0.y + al1 * v1.y;
            acc[j4 * 4 + 2] += al0 * v0.z + al1 * v1.z;
            acc[j4 * 4 + 3] += al0 * v0.w + al1 * v1.w;
        }
    }
    for (; i < end; i += 4) {
        int sn0 = g_srcs[i];
        float al0 = g_alpha_s[(size_t)i * 4 + myh] * myR;
        const float4* p0 = (const float4*)(xl + (size_t)sn0 * CH + lane * V);
#pragma unroll
        for (int j4 = 0; j4 < V / 4; j4++) {
            float4 v0 = p0[j4];
            acc[j4 * 4 + 0] += al0 * v0.x;
            acc[j4 * 4 + 1] += al0 * v0.y;
            acc[j4 * 4 + 2] += al0 * v0.z;
            acc[j4 * 4 + 3] += al0 * v0.w;
        }
    }

    // ---- Phase 3: cross-warp reduce + head-mean + bias ----
#pragma unroll
    for (int j = 0; j < V; j++) sAcc[local][w][lane * V + j] = acc[j];
    __syncthreads();

    int idx = w * 32 + lane;   // 0..127 within this node's thread group
    if (idx < C) {
        float r = 0.f;
#pragma unroll
        for (int ww = 0; ww < 4; ww++)
#pragma unroll
            for (int h = 0; h < 4; h++)
                r += sAcc[local][ww][h * C + idx];
        out[(size_t)node * C + idx] = r * 0.25f + bias[idx];
    }
}

// ---------------- node projections P[n] = out2[n] @ [mW1_src | mW1_dst] ----------------
__global__ __launch_bounds__(256) void build_P_kernel(const float* __restrict__ out2,
                                                      const float* __restrict__ mW1) {
    __shared__ float sWp[32 * 128];
    int tid = threadIdx.x;
    for (int idx = tid; idx < 32 * 128; idx += 256) {
        int k = idx >> 7, j = idx & 127;
        sWp[idx] = (j < 64) ? mW1[k * 64 + j] : mW1[(36 + k) * 64 + (j - 64)];
    }
    __syncthreads();
    int node = (blockIdx.x * 256 + tid) >> 5;
    int lane = tid & 31;
    if (node >= NN) return;
    float own = out2[(size_t)node * 32 + lane];
    float a0 = 0.f, a1 = 0.f, a2 = 0.f, a3 = 0.f;
#pragma unroll
    for (int k = 0; k < 32; k++) {
        float f = __shfl_sync(0xffffffff, own, k);
        a0 += f * sWp[k * 128 + lane];
        a1 += f * sWp[k * 128 + lane + 32];
        a2 += f * sWp[k * 128 + lane + 64];
        a3 += f * sWp[k * 128 + lane + 96];
    }
    float* Pr = &g_P[(size_t)node * 128];
    Pr[lane]      = a0;
    Pr[lane + 32] = a1;
    Pr[lane + 64] = a2;
    Pr[lane + 96] = a3;
}

// ---------------- edge MLP finish (alpha normalization fused): warp per edge ----------------
__global__ __launch_bounds__(256) void edge_mlp_kernel(
    const int* __restrict__ ei,
    const float* __restrict__ mW1, const float* __restrict__ mb1,
    const float* __restrict__ mW2, const float* __restrict__ mb2,
    float* __restrict__ edge_out) {
    __shared__ float sWa[4 * 64];
    __shared__ float sW2[128];
    __shared__ float sb1[64];
    int tid = threadIdx.x;
    sWa[tid] = mW1[(32 + (tid >> 6)) * 64 + (tid & 63)];
    if (tid < 128) sW2[tid] = mW2[tid];
    if (tid < 64)  sb1[tid] = mb1[tid];
    __syncthreads();

    int e = (blockIdx.x * 256 + tid) >> 5;
    int lane = tid & 31;
    if (e >= EE) return;
    int s = ei[e], d = ei[EE + e];
    float4 ex = *(const float4*)&g_alpha[(size_t)e * 4];
    float4 R  = *(const float4*)&g_nodeR[d * 4];
    float4 a;
    a.x = ex.x * R.x;
    a.y = ex.y * R.y;
    a.z = ex.z * R.z;
    a.w = ex.w * R.w;

    const float* Ps = &g_P[(size_t)s * 128];
    const float* Pd = &g_P[(size_t)d * 128 + 64];
    int c0 = lane, c1 = lane + 32;

    float h0 = Ps[c0] + Pd[c0] + sb1[c0]
             + a.x * sWa[c0] + a.y * sWa[64 + c0] + a.z * sWa[128 + c0] + a.w * sWa[192 + c0];
    float h1 = Ps[c1] + Pd[c1] + sb1[c1]
             + a.x * sWa[c1] + a.y * sWa[64 + c1] + a.z * sWa[128 + c1] + a.w * sWa[192 + c1];
    h0 = fmaxf(h0, 0.f);
    h1 = fmaxf(h1, 0.f);
    float s0 = h0 * sW2[c0 * 2 + 0] + h1 * sW2[c1 * 2 + 0];
    float s1 = h0 * sW2[c0 * 2 + 1] + h1 * sW2[c1 * 2 + 1];
#pragma unroll
    for (int off = 16; off; off >>= 1) {
        s0 += __shfl_xor_sync(0xffffffff, s0, off);
        s1 += __shfl_xor_sync(0xffffffff, s1, off);
    }
    if (lane == 0) {
        edge_out[(size_t)e * 2 + 0] = s0 + mb2[0];
        edge_out[(size_t)e * 2 + 1] = s1 + mb2[1];
    }
}

// ---------------- launch ----------------
extern "C" void kernel_launch(void* const* d_in, const int* in_sizes, int n_in,
                              void* d_out, int out_size) {
    const float* x        = (const float*)d_in[0];
    const int*   ei       = (const int*)d_in[1];
    const float* W1       = (const float*)d_in[4];
    const float* att1_src = (const float*)d_in[5];
    const float* att1_dst = (const float*)d_in[6];
    const float* b1       = (const float*)d_in[7];
    const float* W3       = (const float*)d_in[8];
    const float* att3_src = (const float*)d_in[9];
    const float* att3_dst = (const float*)d_in[10];
    const float* b3       = (const float*)d_in[11];
    const float* mW1      = (const float*)d_in[12];
    const float* mb1      = (const float*)d_in[13];
    const float* mW2      = (const float*)d_in[14];
    const float* mb2      = (const float*)d_in[15];

    float* out2     = (float*)d_out;          // [N, 32]
    float* edge_out = out2 + (size_t)NN * 32; // [E, 2]

    zero_counts_kernel<<<(NN + 255) / 256, 256>>>();                                    // 0
    {
        dim3 grid(256 / BN, (NN + BM - 1) / BM);
        sgemm_kernel<<<grid, 256>>>(x, W1, g_xl, NN, 128, 256);                         // 1
    }
    att_dot_kernel<64><<<(NN * 32 + 255) / 256, 256>>>(g_xl, att1_src, att1_dst);       // 2
    hist_kernel<<<(EE + 255) / 256, 256>>>(ei);                                         // 3 <- profiled
    scan_kernel<<<1, 1024>>>();                                                         // 4
    scatter_kernel<<<(EE + 255) / 256, 256>>>(ei);                                      // 5

    // Layer 1
    edge_alpha_kernel<false><<<(EE + 255) / 256, 256>>>(ei);                            // 6
    aggregate2_kernel<64, false><<<NN / 2, 256>>>(g_xl, b1, g_out1);                    // 7

    // Layer 2
    {
        dim3 grid(128 / BN, (NN + BM - 1) / BM);
        sgemm_kernel<<<grid, 256>>>(g_out1, W3, g_xl, NN, 64, 128);                     // 8
    }
    att_dot_kernel<32><<<(NN * 32 + 255) / 256, 256>>>(g_xl, att3_src, att3_dst);       // 9
    edge_alpha_kernel<true><<<(EE + 255) / 256, 256>>>(ei);                             // 10
    aggregate2_kernel<32, true><<<NN / 2, 256>>>(g_xl, b3, out2);                       // 11

    // Edge outputs
    build_P_kernel<<<(NN * 32 + 255) / 256, 256>>>(out2, mW1);                          // 12
    edge_mlp_kernel<<<(EE * 32 + 255) / 256, 256>>>(ei, mW1, mb1, mW2, mb2, edge_out);  // 13
}